// round 1
// baseline (speedup 1.0000x reference)
#include <cuda_runtime.h>
#include <float.h>

// ParabolicPool2D: out[b,c,i,j] = max_{p,q in 0..2} f[b,c,2i+p,2j+q] + h[c,p,q]
// h[c,p,q] = -t[c] * (zp^2 + zq^2) / 2, z = [-1,0,1]
// Separable: with s = t[c]/2,
//   colmax[r][j] = max(f[r][2j]-s, f[r][2j+1], f[r][2j+2]-s)
//   out[i][j]    = max(colmax[2i]-s, colmax[2i+1], colmax[2i+2]-s)

#define Wd 256
#define Hd 256
#define OWd 127
#define OHd 127
#define Cd 128
#define Bd 16

__device__ __forceinline__ void row_colmax(const float* __restrict__ row,
                                           int c0, bool full, float s,
                                           float cm[8]) {
    // 17 input floats: cols c0 .. c0+16 (c0 multiple of 16 -> 16B aligned)
    float4 v0 = __ldg((const float4*)(row + c0));
    float4 v1 = __ldg((const float4*)(row + c0 + 4));
    float4 v2 = __ldg((const float4*)(row + c0 + 8));
    float4 v3 = __ldg((const float4*)(row + c0 + 12));
    float last = full ? __ldg(row + c0 + 16) : -FLT_MAX;
    float in[17] = {v0.x, v0.y, v0.z, v0.w,
                    v1.x, v1.y, v1.z, v1.w,
                    v2.x, v2.y, v2.z, v2.w,
                    v3.x, v3.y, v3.z, v3.w, last};
    float e[9];
#pragma unroll
    for (int k = 0; k < 9; k++) e[k] = in[2 * k] - s;
#pragma unroll
    for (int u = 0; u < 8; u++)
        cm[u] = fmaxf(fmaxf(e[u], in[2 * u + 1]), e[u + 1]);
}

__global__ void __launch_bounds__(256)
parabolic_pool2d_kernel(const float* __restrict__ f,
                        const float* __restrict__ t,
                        float* __restrict__ out) {
    int tid = blockIdx.x * 256 + threadIdx.x;
    int sj = tid & 15;          // column strip: output cols [8*sj, 8*sj+8)
    int ti = (tid >> 4) & 7;    // row tile: output rows [16*ti, 16*ti+16)
    int c  = (tid >> 7) & 127;
    int b  = tid >> 14;

    float s = 0.5f * __ldg(t + c);
    int j0 = sj << 3;
    int i0 = ti << 4;
    bool full = (sj < 15);      // strip 15: only 7 valid outputs, no 17th load

    const float* fp = f + (size_t)(b * Cd + c) * (Hd * Wd);
    float*       op = out + (size_t)(b * Cd + c) * (OHd * OWd);
    int c0 = j0 << 1;           // input col base = 16*sj
    int r0 = i0 << 1;           // input row base

    float cmA[8], cmB[8], cmC[8];
    row_colmax(fp + (size_t)r0 * Wd, c0, full, s, cmA);

    int imax = min(16, OHd - i0);   // 16, or 15 for last row tile
    for (int ii = 0; ii < imax; ii++) {
        const float* rp = fp + (size_t)(r0 + 2 * ii) * Wd;
        row_colmax(rp + Wd,     c0, full, s, cmB);
        row_colmax(rp + 2 * Wd, c0, full, s, cmC);

        float* orow = op + (size_t)(i0 + ii) * OWd + j0;
#pragma unroll
        for (int u = 0; u < 8; u++) {
            float v = fmaxf(fmaxf(cmA[u] - s, cmB[u]), cmC[u] - s);
            if (full || u < 7) orow[u] = v;
        }
#pragma unroll
        for (int u = 0; u < 8; u++) cmA[u] = cmC[u];
    }
}

extern "C" void kernel_launch(void* const* d_in, const int* in_sizes, int n_in,
                              void* d_out, int out_size) {
    const float* f = (const float*)d_in[0];   // [16,128,256,256] fp32
    const float* t = (const float*)d_in[1];   // [128] fp32
    float* out = (float*)d_out;               // [16,128,127,127] fp32
    // ks=3, stride=2 hardcoded (d_in[2], d_in[3] if present are constants)
    // total threads = B(16) * C(128) * row_tiles(8) * col_strips(16) = 262144
    parabolic_pool2d_kernel<<<1024, 256>>>(f, t, out);
}

// round 2
// speedup vs baseline: 1.5583x; 1.5583x over previous
#include <cuda_runtime.h>
#include <float.h>

// ParabolicPool2D: out[b,c,i,j] = max_{p,q in 0..2} f[b,c,2i+p,2j+q] + h[c,p,q]
// h[c,p,q] = -t[c]*(zp^2+zq^2)/2, z=[-1,0,1]  -> separable with s = t[c]/2:
//   colmax[r][j] = max(f[r][2j]-s, f[r][2j+1], f[r][2j+2]-s)
//   out[i][j]    = max(colmax[2i]-s, colmax[2i+1], colmax[2i+2]-s)
//
// Coalescing layout: lane owns chunks at cols [4L,4L+4) and [4L+128,4L+132).
// Every LDG.128 is 32 lanes x 16B contiguous (512B). Neighbor element for the
// odd colmax comes from lane+1 via shuffle (lane 0 feeds lane 31 its chunk-1 head).

#define Wd 256
#define Hd 256
#define OWd 127
#define OHd 127
#define Cd 128

__device__ __forceinline__ void row_colmax2(const float* __restrict__ row,
                                            int lane, float s, float cm[4]) {
    float4 v0 = __ldcs((const float4*)(row + 4 * lane));
    float4 v1 = __ldcs((const float4*)(row + 4 * lane + 128));
    // value this lane exports to lane-1 (lane 0 exports chunk-1 head to lane 31)
    float h0 = (lane == 0) ? v1.x : v0.x;
    float h1 = v1.x;                       // lane 0's export here is unused garbage
    int src = (lane + 1) & 31;
    float n0 = __shfl_sync(0xffffffffu, h0, src);  // col 4*lane+4
    float n1 = __shfl_sync(0xffffffffu, h1, src);  // col 4*lane+132 (invalid for lane 31)
    cm[0] = fmaxf(fmaxf(v0.x - s, v0.y), v0.z - s);   // out col 2*lane
    cm[1] = fmaxf(fmaxf(v0.z - s, v0.w), n0 - s);     // out col 2*lane+1
    cm[2] = fmaxf(fmaxf(v1.x - s, v1.y), v1.z - s);   // out col 2*lane+64
    cm[3] = fmaxf(fmaxf(v1.z - s, v1.w), n1 - s);     // out col 2*lane+65 (lane31: unused)
}

__global__ void __launch_bounds__(256)
parabolic_pool2d_kernel(const float* __restrict__ f,
                        const float* __restrict__ t,
                        float* __restrict__ out) {
    int tid  = blockIdx.x * 256 + threadIdx.x;
    int lane = tid & 31;            // column owner within row
    int ti   = (tid >> 5) & 7;      // row tile: output rows [16*ti, 16*ti+16)
    int c    = (tid >> 8) & 127;
    int b    = tid >> 15;

    float s = 0.5f * __ldg(t + c);

    const float* fp = f + (size_t)(b * Cd + c) * (Hd * Wd);
    float*       op = out + (size_t)(b * Cd + c) * (OHd * OWd);

    int i0 = ti << 4;
    int r0 = i0 << 1;
    int j0 = 2 * lane;
    bool lastlane = (lane == 31);

    float cmA[4], cmB[4], cmC[4];
    row_colmax2(fp + (size_t)r0 * Wd, lane, s, cmA);

    int imax = min(16, OHd - i0);   // 16, or 15 for the last row tile
    for (int ii = 0; ii < imax; ii++) {
        const float* rp = fp + (size_t)(r0 + 2 * ii) * Wd;
        row_colmax2(rp + Wd,     lane, s, cmB);
        row_colmax2(rp + 2 * Wd, lane, s, cmC);

        float o0 = fmaxf(fmaxf(cmA[0] - s, cmB[0]), cmC[0] - s);
        float o1 = fmaxf(fmaxf(cmA[1] - s, cmB[1]), cmC[1] - s);
        float o2 = fmaxf(fmaxf(cmA[2] - s, cmB[2]), cmC[2] - s);
        float o3 = fmaxf(fmaxf(cmA[3] - s, cmB[3]), cmC[3] - s);

        float* orow = op + (size_t)(i0 + ii) * OWd;
        orow[j0]      = o0;
        orow[j0 + 1]  = o1;
        orow[j0 + 64] = o2;
        if (!lastlane) orow[j0 + 65] = o3;

#pragma unroll
        for (int u = 0; u < 4; u++) cmA[u] = cmC[u];
    }
}

extern "C" void kernel_launch(void* const* d_in, const int* in_sizes, int n_in,
                              void* d_out, int out_size) {
    const float* f = (const float*)d_in[0];   // [16,128,256,256] fp32
    const float* t = (const float*)d_in[1];   // [128] fp32
    float* out = (float*)d_out;               // [16,128,127,127] fp32
    // threads = B(16) * C(128) * row_tiles(8) * lanes(32) = 524288 -> 2048 blocks
    parabolic_pool2d_kernel<<<2048, 256>>>(f, t, out);
}

// round 3
// speedup vs baseline: 1.7954x; 1.1521x over previous
#include <cuda_runtime.h>
#include <float.h>

// ParabolicPool2D: out[b,c,i,j] = max_{p,q in 0..2} f[b,c,2i+p,2j+q] + h[c,p,q]
// h[c,p,q] = -t[c]*(zp^2+zq^2)/2 -> separable with s = t[c]/2:
//   colmax[r][j] = max(f[r][2j]-s, f[r][2j+1], f[r][2j+2]-s)
//   out[i][j]    = max(colmax[2i]-s, colmax[2i+1], colmax[2i+2]-s)
//
// Lane L owns input cols [4L,4L+4) and [4L+128,4L+132): every LDG.128 is a
// contiguous 512B warp transaction. Neighbor element via __shfl. Row loop is
// unrolled x2: 8 LDG.128 issued back-to-back (MLP=8), then all compute.

#define Wd 256
#define Hd 256
#define OWd 127
#define OHd 127
#define Cd 128

struct Row { float4 a, b; };

__device__ __forceinline__ Row row_load(const float* __restrict__ row, int lane) {
    Row r;
    r.a = __ldcs((const float4*)(row + 4 * lane));
    r.b = __ldcs((const float4*)(row + 4 * lane + 128));
    return r;
}

__device__ __forceinline__ void row_cm(const Row& r, int lane, float s, float cm[4]) {
    float h0 = (lane == 0) ? r.b.x : r.a.x;
    int src = (lane + 1) & 31;
    float n0 = __shfl_sync(0xffffffffu, h0, src);      // col 4L+4 (lane31 <- lane0.b.x)
    float n1 = __shfl_sync(0xffffffffu, r.b.x, src);   // col 4L+132 (lane31: unused)
    cm[0] = fmaxf(fmaxf(r.a.x - s, r.a.y), r.a.z - s); // out col 2L
    cm[1] = fmaxf(fmaxf(r.a.z - s, r.a.w), n0 - s);    // out col 2L+1
    cm[2] = fmaxf(fmaxf(r.b.x - s, r.b.y), r.b.z - s); // out col 2L+64
    cm[3] = fmaxf(fmaxf(r.b.z - s, r.b.w), n1 - s);    // out col 2L+65
}

__device__ __forceinline__ void emit_row(float* __restrict__ orow, int j0,
                                         bool lastlane, float s,
                                         const float cmT[4], const float cmM[4],
                                         const float cmB[4]) {
    float o0 = fmaxf(fmaxf(cmT[0] - s, cmM[0]), cmB[0] - s);
    float o1 = fmaxf(fmaxf(cmT[1] - s, cmM[1]), cmB[1] - s);
    float o2 = fmaxf(fmaxf(cmT[2] - s, cmM[2]), cmB[2] - s);
    float o3 = fmaxf(fmaxf(cmT[3] - s, cmM[3]), cmB[3] - s);
    __stcs(orow + j0, o0);
    __stcs(orow + j0 + 1, o1);
    __stcs(orow + j0 + 64, o2);
    if (!lastlane) __stcs(orow + j0 + 65, o3);
}

__global__ void __launch_bounds__(256)
parabolic_pool2d_kernel(const float* __restrict__ f,
                        const float* __restrict__ t,
                        float* __restrict__ out) {
    int tid  = blockIdx.x * 256 + threadIdx.x;
    int lane = tid & 31;            // column owner within row
    int ti   = (tid >> 5) & 7;      // row tile: output rows [16*ti, 16*ti+16)
    int c    = (tid >> 8) & 127;
    int b    = tid >> 15;

    float s = 0.5f * __ldg(t + c);

    const float* fp = f + (size_t)(b * Cd + c) * (Hd * Wd);
    float*       op = out + (size_t)(b * Cd + c) * (OHd * OWd);

    int i0 = ti << 4;
    int r0 = i0 << 1;
    int j0 = 2 * lane;
    bool lastlane = (lane == 31);

    float cmA[4];
    {
        Row A = row_load(fp + (size_t)r0 * Wd, lane);
        row_cm(A, lane, s, cmA);
    }

    int imax = min(16, OHd - i0);   // 16, or 15 for the last row tile
    int ii = 0;
    for (; ii + 2 <= imax; ii += 2) {
        const float* rp = fp + (size_t)(r0 + 2 * ii) * Wd;
        // ---- load phase: 8 back-to-back LDG.128 ----
        Row B = row_load(rp + 1 * Wd, lane);
        Row C = row_load(rp + 2 * Wd, lane);
        Row D = row_load(rp + 3 * Wd, lane);
        Row E = row_load(rp + 4 * Wd, lane);
        // ---- compute phase ----
        float cmB[4], cmC[4], cmD[4], cmE[4];
        row_cm(B, lane, s, cmB);
        row_cm(C, lane, s, cmC);
        row_cm(D, lane, s, cmD);
        row_cm(E, lane, s, cmE);

        float* orow = op + (size_t)(i0 + ii) * OWd;
        emit_row(orow,       j0, lastlane, s, cmA, cmB, cmC);
        emit_row(orow + OWd, j0, lastlane, s, cmC, cmD, cmE);
#pragma unroll
        for (int u = 0; u < 4; u++) cmA[u] = cmE[u];
    }
    if (ii < imax) {                // odd tail (last row tile only)
        const float* rp = fp + (size_t)(r0 + 2 * ii) * Wd;
        Row B = row_load(rp + 1 * Wd, lane);
        Row C = row_load(rp + 2 * Wd, lane);
        float cmB[4], cmC[4];
        row_cm(B, lane, s, cmB);
        row_cm(C, lane, s, cmC);
        emit_row(op + (size_t)(i0 + ii) * OWd, j0, lastlane, s, cmA, cmB, cmC);
    }
}

extern "C" void kernel_launch(void* const* d_in, const int* in_sizes, int n_in,
                              void* d_out, int out_size) {
    const float* f = (const float*)d_in[0];   // [16,128,256,256] fp32
    const float* t = (const float*)d_in[1];   // [128] fp32
    float* out = (float*)d_out;               // [16,128,127,127] fp32
    // threads = B(16) * C(128) * row_tiles(8) * lanes(32) = 524288 -> 2048 blocks
    parabolic_pool2d_kernel<<<2048, 256>>>(f, t, out);
}